// round 16
// baseline (speedup 1.0000x reference)
#include <cuda_runtime.h>
#include <math.h>

#define BB 8
#define NN 1024
#define EE 49152
#define DD 256
#define NNZ (EE + NN)         // 50176 per sample
#define KN 717
#define ROWS_OUT (BB * KN)    // 5736

// ---------------- device scratch (no allocations allowed) ----------------
static __device__ float    d_S[BB * NN * NN];      // S, then A (in place)
static __device__ int      d_C[BB * NN * NN];      // multiplicity
static __device__ int      d_deg[BB * NN];
static __device__ float    d_dinv[BB * NN];
static __device__ int      d_rowptr[BB * (NN + 1)];
static __device__ int      d_cursor[BB * NN];
static __device__ int      d_col[BB * NNZ];
static __device__ float    d_val[BB * NNZ];
static __device__ float    d_x0[BB * NN * DD];
static __device__ float    d_x1[BB * NN * DD];     // pagerank ping-pong, later pooled rows
static __device__ float    d_xcut[BB * NN * DD];
static __device__ float    d_u[DD];
static __device__ float    d_v[DD];
static __device__ float    d_ssrc[BB * NN];
static __device__ float    d_stgt[BB * NN];
static __device__ int      d_M[BB];
static __device__ unsigned d_h1[BB * 4096];
static __device__ unsigned d_h2lo[BB * 4096];
static __device__ unsigned d_h2hi[BB * 4096];
static __device__ unsigned d_h3lo[BB * 256];
static __device__ unsigned d_h3hi[BB * 256];
static __device__ int      d_rankLo[BB], d_rankHi[BB];
static __device__ unsigned d_prefLo[BB], d_prefHi[BB];
static __device__ float    d_frac[BB], d_cutv[BB];
static __device__ float    d_score[BB * NN];
static __device__ int      d_perm[BB * KN];
static __device__ float    d_WT[512 * 256];

// ---------------- kernels ----------------

// zero scratch + init x0/xcut (fused; numerically identical to R8's k_zero + k_init)
__global__ void k_zero(const float* __restrict__ x, const float* __restrict__ temp) {
    int i = blockIdx.x * blockDim.x + threadIdx.x;
    int stride = gridDim.x * blockDim.x;
    float t0 = temp[0];
    for (int j = i; j < BB * NN * NN; j += stride) { d_S[j] = 0.f; d_C[j] = 0; }
    for (int j = i; j < BB * NN * DD; j += stride) {
        float vv = x[j];
        d_x0[j] = vv;
        d_xcut[j] = t0 * vv;
    }
    for (int j = i; j < BB * 4096; j += stride) { d_h1[j] = 0u; d_h2lo[j] = 0u; d_h2hi[j] = 0u; }
    for (int j = i; j < BB * 256; j += stride) { d_h3lo[j] = 0u; d_h3hi[j] = 0u; }
    for (int j = i; j < BB * NN; j += stride) d_deg[j] = 0;
    if (i < BB) d_M[i] = 0;
}

__global__ void k_deg(const int* __restrict__ tail) {
    int idx = blockIdx.x * blockDim.x + threadIdx.x;
    if (idx >= BB * EE) return;
    int b = idx / EE;
    atomicAdd(&d_deg[b * NN + tail[idx]], 1);
}

// rowptr prefix-scan + dinv (fused; same formulas as R8's k_dinv + k_rowptr)
__global__ void k_rowptr() {
    int b = blockIdx.x, t = threadIdx.x;
    __shared__ int sm[NN];
    int cnt = d_deg[b * NN + t] + 1;
    // deg includes +1 self-loop; correctly-rounded f32 1/sqrt via double
    d_dinv[b * NN + t] = (float)(1.0 / sqrt((double)cnt));
    sm[t] = cnt;
    __syncthreads();
    for (int off = 1; off < NN; off <<= 1) {
        int v = (t >= off) ? sm[t - off] : 0;
        __syncthreads();
        sm[t] += v;
        __syncthreads();
    }
    d_rowptr[b * (NN + 1) + t + 1] = sm[t];
    if (t == 0) d_rowptr[b * (NN + 1)] = 0;
    d_cursor[b * NN + t] = sm[t] - cnt;
}

// self-loops first, then edges: preserves R8's per-row CSR fill order exactly
__global__ void k_fill_self() {
    int idx = blockIdx.x * blockDim.x + threadIdx.x;
    if (idx >= BB * NN) return;
    int b = idx / NN, n = idx - b * NN;
    int slot = atomicAdd(&d_cursor[idx], 1);
    float dv = d_dinv[idx];
    d_col[b * NNZ + slot] = n;
    d_val[b * NNZ + slot] = dv * dv;
}

__global__ void k_fill_edges(const int* __restrict__ head, const int* __restrict__ tail) {
    int idx = blockIdx.x * blockDim.x + threadIdx.x;
    if (idx >= BB * EE) return;
    int b = idx / EE;
    int h = head[idx], t = tail[idx];
    int slot = atomicAdd(&d_cursor[b * NN + t], 1);
    d_col[b * NNZ + slot] = h;
    d_val[b * NNZ + slot] = d_dinv[b * NN + h] * d_dinv[b * NN + t];
}

// gather SpMM; accumulation order = ascending CSR index = bit-identical to R8's
// tiled loop. Direct warp-uniform __ldg broadcasts, no smem staging / syncs.
__global__ void k_spmm(const float* __restrict__ temp, int step) {
    const float* __restrict__ xin = (step & 1) ? d_x0 : d_x1;
    float* __restrict__ xout      = (step & 1) ? d_x1 : d_x0;
    int b = blockIdx.y, row = blockIdx.x, tid = threadIdx.x;
    int start = d_rowptr[b * (NN + 1) + row];
    int end   = d_rowptr[b * (NN + 1) + row + 1];
    float tk = temp[step];
    const int*   __restrict__ cp = d_col + (size_t)b * NNZ;
    const float* __restrict__ vp = d_val + (size_t)b * NNZ;
    const float* __restrict__ xb = xin + (size_t)b * NN * DD;
    float acc = 0.f;
    #pragma unroll 4
    for (int i = start; i < end; i++) {
        int c   = __ldg(&cp[i]);
        float w = __ldg(&vp[i]);
        acc += w * __ldg(&xb[c * DD + tid]);
    }
    int o = (b * NN + row) * DD + tid;
    xout[o] = acc;
    d_xcut[o] += tk * acc;
}

__global__ void k_uv(const float* __restrict__ Wp, const float* __restrict__ a_src,
                     const float* __restrict__ a_tgt) {
    int which = blockIdx.x, i = threadIdx.x;
    const float* a = which ? a_tgt : a_src;
    float acc = 0.f;
    for (int o = 0; o < DD; o++) acc += Wp[o * DD + i] * a[o];
    if (which) d_v[i] = acc; else d_u[i] = acc;
}

__global__ void k_scores() {
    int warp = threadIdx.x >> 5, lane = threadIdx.x & 31;
    int g = blockIdx.x * 8 + warp;  // node-global index over BB*NN
    const float* xr = d_xcut + (size_t)g * DD;
    float su = 0.f, svv = 0.f;
    for (int d = lane; d < DD; d += 32) {
        float xv = xr[d];
        su += xv * d_u[d];
        svv += xv * d_v[d];
    }
    for (int o = 16; o; o >>= 1) {
        su += __shfl_down_sync(0xFFFFFFFFu, su, o);
        svv += __shfl_down_sync(0xFFFFFFFFu, svv, o);
    }
    if (!lane) { d_ssrc[g] = su; d_stgt[g] = svv; }
}

__global__ void k_scatter(const int* __restrict__ head, const int* __restrict__ tail) {
    int idx = blockIdx.x * blockDim.x + threadIdx.x;
    if (idx >= BB * EE) return;
    int b = idx / EE;
    int h = head[idx], t = tail[idx];
    float z = d_ssrc[b * NN + h] + d_stgt[b * NN + t];
    // correctly-rounded double sigmoid: immune to --use_fast_math expf approximation,
    // which perturbed edge ordering near the percentile cut (R5 failure, rel_err 2.4e-2).
    float a = (float)(1.0 / (1.0 + exp(-(double)z)));
    int base = b * NN * NN;
    atomicAdd(&d_S[base + h * NN + t], a);
    atomicAdd(&d_S[base + t * NN + h], a);
    atomicAdd(&d_C[base + h * NN + t], 1);
    atomicAdd(&d_C[base + t * NN + h], 1);
}

__global__ void k_finalize() {
    int b = blockIdx.y, row = blockIdx.x, tid = threadIdx.x;
    __shared__ unsigned hist[4096];
    __shared__ int cntS;
    for (int q = tid; q < 4096; q += 256) hist[q] = 0u;
    if (tid == 0) cntS = 0;
    __syncthreads();
    int base = (b * NN + row) * NN;
    int myc = 0;
    for (int q = 0; q < 4; q++) {
        int j = q * 256 + tid;
        int c = d_C[base + j];
        float A = 0.f;
        if (c > 0) {
            A = __fdiv_rn(d_S[base + j], (float)c);
            myc++;
            atomicAdd(&hist[__float_as_uint(A) >> 20], 1u);
        }
        d_S[base + j] = A;
    }
    atomicAdd(&cntS, myc);
    __syncthreads();
    if (tid == 0) atomicAdd(&d_M[b], cntS);
    for (int q = tid; q < 4096; q += 256) {
        unsigned hv = hist[q];
        if (hv) atomicAdd(&d_h1[b * 4096 + q], hv);
    }
}

__global__ void k_select(int level) {
    int b = blockIdx.x, t = threadIdx.x;
    __shared__ unsigned part[256];
    __shared__ unsigned spre[256];
    if (level == 1 && t == 0) {
        int M = d_M[b];
        float pos = 0.2f * (float)(M - 1);
        float fl = floorf(pos);
        int lo = (int)fl;
        float frac = pos - fl;
        int hi = lo + 1; if (hi > M - 1) hi = M - 1;
        d_rankLo[b] = lo; d_rankHi[b] = hi; d_frac[b] = frac;
    }
    __syncthreads();
    int nb = (level == 3) ? 256 : 4096;
    int chunk = nb / 256;
    for (int p = 0; p < 2; p++) {
        const unsigned* hist;
        if (level == 1)      hist = d_h1 + b * 4096;
        else if (level == 2) hist = (p ? d_h2hi : d_h2lo) + b * 4096;
        else                 hist = (p ? d_h3hi : d_h3lo) + b * 256;
        int rank = p ? d_rankHi[b] : d_rankLo[b];
        unsigned c = 0;
        for (int q = 0; q < chunk; q++) c += hist[t * chunk + q];
        part[t] = c;
        spre[t] = c;
        __syncthreads();
        for (int off = 1; off < 256; off <<= 1) {
            unsigned w = (t >= off) ? spre[t - off] : 0u;
            __syncthreads();
            spre[t] += w;
            __syncthreads();
        }
        unsigned pre = spre[t] - part[t];  // exclusive prefix
        if ((unsigned)rank >= pre && (unsigned)rank < pre + part[t]) {
            unsigned r2 = (unsigned)rank - pre;
            int bin = 0;
            for (int q = 0; q < chunk; q++) {
                unsigned hv = hist[t * chunk + q];
                if (r2 < hv) { bin = t * chunk + q; break; }
                r2 -= hv;
            }
            unsigned prev = p ? d_prefHi[b] : d_prefLo[b];
            unsigned npref = (level == 1) ? (unsigned)bin
                             : ((prev << ((level == 2) ? 12 : 8)) | (unsigned)bin);
            if (p) { d_prefHi[b] = npref; d_rankHi[b] = (int)r2; }
            else   { d_prefLo[b] = npref; d_rankLo[b] = (int)r2; }
        }
        __syncthreads();
    }
    if (level == 3 && t == 0) {
        float svlo = __uint_as_float(d_prefLo[b]);
        float svhi = __uint_as_float(d_prefHi[b]);
        d_cutv[b] = svlo + d_frac[b] * (svhi - svlo);
    }
}

__global__ void k_hist2() {
    int b = blockIdx.y, row = blockIdx.x, tid = threadIdx.x;
    int base = (b * NN + row) * NN;
    unsigned pl = d_prefLo[b], ph = d_prefHi[b];
    for (int q = 0; q < 4; q++) {
        float A = d_S[base + q * 256 + tid];
        if (A > 0.f) {
            unsigned bits = __float_as_uint(A);
            unsigned top = bits >> 20, mid = (bits >> 8) & 0xFFFu;
            if (top == pl) atomicAdd(&d_h2lo[b * 4096 + mid], 1u);
            if (top == ph) atomicAdd(&d_h2hi[b * 4096 + mid], 1u);
        }
    }
}

__global__ void k_hist3() {
    int b = blockIdx.y, row = blockIdx.x, tid = threadIdx.x;
    int base = (b * NN + row) * NN;
    unsigned pl = d_prefLo[b], ph = d_prefHi[b];
    for (int q = 0; q < 4; q++) {
        float A = d_S[base + q * 256 + tid];
        if (A > 0.f) {
            unsigned bits = __float_as_uint(A);
            unsigned top24 = bits >> 8, low = bits & 0xFFu;
            if (top24 == pl) atomicAdd(&d_h3lo[b * 256 + low], 1u);
            if (top24 == ph) atomicAdd(&d_h3hi[b * 256 + low], 1u);
        }
    }
}

// Compacted row-gather: acc = sum over kept entries of row of mat (NN wide), gathering x rows.
__device__ __forceinline__ float rowgather(const float* __restrict__ matrow, float cutv,
                                           const float* __restrict__ xb, int tid,
                                           int* sidx, float* sval) {
    const float4* ar = (const float4*)matrow;
    float4 v = ar[tid];
    int c = (v.x >= cutv) + (v.y >= cutv) + (v.z >= cutv) + (v.w >= cutv);
    __shared__ int stmp[256];
    stmp[tid] = c;
    __syncthreads();
    for (int off = 1; off < 256; off <<= 1) {
        int w = (tid >= off) ? stmp[tid - off] : 0;
        __syncthreads();
        stmp[tid] += w;
        __syncthreads();
    }
    int wbase = stmp[tid] - c;  // exclusive
    int col = 4 * tid;
    if (v.x >= cutv) { sidx[wbase] = col;     sval[wbase] = v.x; wbase++; }
    if (v.y >= cutv) { sidx[wbase] = col + 1; sval[wbase] = v.y; wbase++; }
    if (v.z >= cutv) { sidx[wbase] = col + 2; sval[wbase] = v.z; wbase++; }
    if (v.w >= cutv) { sidx[wbase] = col + 3; sval[wbase] = v.w; }
    __syncthreads();
    int nnz = stmp[255];
    float acc = 0.f;
    #pragma unroll 8
    for (int i = 0; i < nnz; i++)
        acc += sval[i] * __ldg(&xb[sidx[i] * DD + tid]);
    return acc;
}

// A is symmetric => A_cut^T @ x rows == A_cut @ x rows. Compute each row once:
// store it (pooled candidates, into d_x1) and reduce |.| for the node score.
__global__ void k_outpool(const float* __restrict__ x) {
    int b = blockIdx.y, row = blockIdx.x, tid = threadIdx.x;
    __shared__ int   sidx[NN];
    __shared__ float sval[NN];
    __shared__ float red[256];
    float acc = rowgather(d_S + ((size_t)b * NN + row) * NN, d_cutv[b],
                          x + (size_t)b * NN * DD, tid, sidx, sval);
    d_x1[((size_t)b * NN + row) * DD + tid] = acc;
    red[tid] = fabsf(acc);
    __syncthreads();
    for (int off = 128; off; off >>= 1) {
        if (tid < off) red[tid] += red[tid + off];
        __syncthreads();
    }
    if (tid == 0) d_score[b * NN + row] = red[0] + 1e-7f;
}

__global__ void k_topk() {
    int b = blockIdx.x, t = threadIdx.x;
    __shared__ unsigned long long key[NN];
    float s = d_score[b * NN + t];
    unsigned bits = __float_as_uint(s);
    bits ^= (bits & 0x80000000u) ? 0xFFFFFFFFu : 0x80000000u;  // ascending orderable
    unsigned desc = ~bits;                                      // descending score
    key[t] = ((unsigned long long)desc << 32) | (unsigned)t;
    __syncthreads();
    for (int k = 2; k <= NN; k <<= 1) {
        for (int j = k >> 1; j > 0; j >>= 1) {
            int ixj = t ^ j;
            if (ixj > t) {
                bool up = ((t & k) == 0);
                unsigned long long a = key[t], bb2 = key[ixj];
                if ((a > bb2) == up) { key[t] = bb2; key[ixj] = a; }
            }
            __syncthreads();
        }
    }
    if (t < KN) d_perm[b * KN + t] = (int)(key[t] & 0xFFFFFFFFu);
}

__global__ void k_wt(const float* __restrict__ Wlin) {
    int j = blockIdx.x, o = threadIdx.x;
    d_WT[j * 256 + o] = Wlin[o * 512 + j];
}

__global__ void k_gemm(const float* __restrict__ x, const float* __restrict__ b_lin,
                       float* __restrict__ out) {
    int tile = blockIdx.x, t = threadIdx.x;
    __shared__ float sh[16][512];
    int gr0 = tile * 16;
    for (int r = 0; r < 16; r++) {
        int gr = gr0 + r;
        if (gr < ROWS_OUT) {
            int b = gr / KN, i = gr - b * KN;
            int p = d_perm[b * KN + i];
            sh[r][t]       = x[((size_t)b * NN + p) * DD + t];
            sh[r][256 + t] = d_x1[((size_t)b * NN + p) * DD + t];  // pooled row
        } else {
            sh[r][t] = 0.f; sh[r][256 + t] = 0.f;
        }
    }
    __syncthreads();
    float acc[16];
    #pragma unroll
    for (int r = 0; r < 16; r++) acc[r] = 0.f;
    for (int j = 0; j < 512; j++) {
        float w = d_WT[j * 256 + t];
        #pragma unroll
        for (int r = 0; r < 16; r++) acc[r] += sh[r][j] * w;
    }
    float bl = b_lin[t];
    for (int r = 0; r < 16; r++) {
        int gr = gr0 + r;
        if (gr < ROWS_OUT) out[(size_t)gr * DD + t] = acc[r] + bl;
    }
}

__global__ void k_misc(const int* __restrict__ labels, const int* __restrict__ ids,
                       float* __restrict__ out, int out_size) {
    int idx = blockIdx.x * blockDim.x + threadIdx.x;
    if (idx >= ROWS_OUT) return;
    int b = idx / KN, i = idx - b * KN;
    int p = d_perm[b * KN + i];
    if (out_size >= ROWS_OUT * DD + ROWS_OUT)
        out[ROWS_OUT * DD + idx] = (float)labels[b * NN + p];
    if (out_size >= ROWS_OUT * DD + 2 * ROWS_OUT)
        out[ROWS_OUT * DD + ROWS_OUT + idx] = (float)ids[b * NN + p];
}

// ---------------- launch ----------------
extern "C" void kernel_launch(void* const* d_in, const int* in_sizes, int n_in,
                              void* d_out, int out_size) {
    const float* ch     = (const float*)d_in[0];   // concept_hidden [8,1024,256]
    const int*   head   = (const int*)d_in[2];     // [8,49152]
    const int*   tail   = (const int*)d_in[3];
    const int*   labels = (const int*)d_in[5];     // [8,1024]
    const int*   ids    = (const int*)d_in[6];
    const float* temp   = (const float*)d_in[7];   // [11]
    const float* Wp     = (const float*)d_in[8];   // [256,256]
    const float* a_src  = (const float*)d_in[9];
    const float* a_tgt  = (const float*)d_in[10];
    const float* Wlin   = (const float*)d_in[11];  // [256,512]
    const float* b_lin  = (const float*)d_in[12];
    float* out = (float*)d_out;

    // launch indices 0-4 are setup; index 5 = first k_spmm (ncu -s 5 capture target)
    k_zero<<<1184, 256>>>(ch, temp);                                 // 0
    k_deg<<<(BB * EE + 255) / 256, 256>>>(tail);                     // 1
    k_rowptr<<<BB, NN>>>();                                          // 2
    k_fill_self<<<(BB * NN + 255) / 256, 256>>>();                   // 3
    k_fill_edges<<<(BB * EE + 255) / 256, 256>>>(head, tail);        // 4
    for (int s = 1; s <= 10; s++)
        k_spmm<<<dim3(NN, BB), DD>>>(temp, s);                       // 5..14
    k_uv<<<2, DD>>>(Wp, a_src, a_tgt);
    k_scores<<<(BB * NN) / 8, 256>>>();
    k_scatter<<<(BB * EE + 255) / 256, 256>>>(head, tail);
    k_finalize<<<dim3(NN, BB), 256>>>();
    k_select<<<BB, 256>>>(1);
    k_hist2<<<dim3(NN, BB), 256>>>();
    k_select<<<BB, 256>>>(2);
    k_hist3<<<dim3(NN, BB), 256>>>();
    k_select<<<BB, 256>>>(3);
    k_outpool<<<dim3(NN, BB), 256>>>(ch);
    k_topk<<<BB, NN>>>();
    k_wt<<<512, 256>>>(Wlin);
    k_gemm<<<(ROWS_OUT + 15) / 16, 256>>>(ch, b_lin, out);
    k_misc<<<(ROWS_OUT + 255) / 256, 256>>>(labels, ids, out, out_size);
}

// round 17
// speedup vs baseline: 1.7502x; 1.7502x over previous
#include <cuda_runtime.h>
#include <math.h>

#define BB 8
#define NN 1024
#define EE 49152
#define DD 256
#define NNZ (EE + NN)         // 50176 per sample
#define KN 717
#define ROWS_OUT (BB * KN)    // 5736

// ---------------- device scratch (no allocations allowed) ----------------
static __device__ float    d_S[BB * NN * NN];      // S, then A (in place)
static __device__ int      d_C[BB * NN * NN];      // multiplicity
static __device__ int      d_deg[BB * NN];
static __device__ float    d_dinv[BB * NN];
static __device__ int      d_rowptr[BB * (NN + 1)];
static __device__ int      d_cursor[BB * NN];
static __device__ int      d_col[BB * NNZ];
static __device__ float    d_val[BB * NNZ];
static __device__ float    d_x0[BB * NN * DD];
static __device__ float    d_x1[BB * NN * DD];     // pagerank ping-pong, later pooled rows
static __device__ float    d_xcut[BB * NN * DD];
static __device__ float    d_u[DD];
static __device__ float    d_v[DD];
static __device__ float    d_ssrc[BB * NN];
static __device__ float    d_stgt[BB * NN];
static __device__ int      d_M[BB];
static __device__ unsigned d_h1[BB * 4096];
static __device__ unsigned d_h2lo[BB * 4096];
static __device__ unsigned d_h2hi[BB * 4096];
static __device__ unsigned d_h3lo[BB * 256];
static __device__ unsigned d_h3hi[BB * 256];
static __device__ int      d_rankLo[BB], d_rankHi[BB];
static __device__ unsigned d_prefLo[BB], d_prefHi[BB];
static __device__ float    d_frac[BB], d_cutv[BB];
static __device__ float    d_score[BB * NN];
static __device__ int      d_perm[BB * KN];
static __device__ float    d_WT[512 * 256];

// ---------------- kernels ----------------

// zero scratch + init x0/xcut (fused; numerically identical to R8's k_zero + k_init)
__global__ void k_zero(const float* __restrict__ x, const float* __restrict__ temp) {
    int i = blockIdx.x * blockDim.x + threadIdx.x;
    int stride = gridDim.x * blockDim.x;
    float t0 = temp[0];
    for (int j = i; j < BB * NN * NN; j += stride) { d_S[j] = 0.f; d_C[j] = 0; }
    for (int j = i; j < BB * NN * DD; j += stride) {
        float vv = x[j];
        d_x0[j] = vv;
        d_xcut[j] = t0 * vv;
    }
    for (int j = i; j < BB * 4096; j += stride) { d_h1[j] = 0u; d_h2lo[j] = 0u; d_h2hi[j] = 0u; }
    for (int j = i; j < BB * 256; j += stride) { d_h3lo[j] = 0u; d_h3hi[j] = 0u; }
    for (int j = i; j < BB * NN; j += stride) d_deg[j] = 0;
    if (i < BB) d_M[i] = 0;
}

__global__ void k_deg(const int* __restrict__ tail) {
    int idx = blockIdx.x * blockDim.x + threadIdx.x;
    if (idx >= BB * EE) return;
    int b = idx / EE;
    atomicAdd(&d_deg[b * NN + tail[idx]], 1);
}

// rowptr prefix-scan + dinv + self-loop CSR entry (fused).
// Self-loop is ALWAYS the first entry of each row (matches R8's fill order:
// k_fill_self ran before k_fill_edges, so slot == row base). Cursor = base+1.
__global__ void k_rowptr() {
    int b = blockIdx.x, t = threadIdx.x;
    __shared__ int sm[NN];
    int cnt = d_deg[b * NN + t] + 1;
    // deg includes +1 self-loop; correctly-rounded f32 1/sqrt via double
    float dv = (float)(1.0 / sqrt((double)cnt));
    d_dinv[b * NN + t] = dv;
    sm[t] = cnt;
    __syncthreads();
    for (int off = 1; off < NN; off <<= 1) {
        int v = (t >= off) ? sm[t - off] : 0;
        __syncthreads();
        sm[t] += v;
        __syncthreads();
    }
    d_rowptr[b * (NN + 1) + t + 1] = sm[t];
    if (t == 0) d_rowptr[b * (NN + 1)] = 0;
    int base = sm[t] - cnt;             // exclusive prefix = row base
    d_col[b * NNZ + base] = t;          // self-loop first
    d_val[b * NNZ + base] = dv * dv;
    d_cursor[b * NN + t] = base + 1;    // edges append after
}

__global__ void k_fill_edges(const int* __restrict__ head, const int* __restrict__ tail) {
    int idx = blockIdx.x * blockDim.x + threadIdx.x;
    if (idx >= BB * EE) return;
    int b = idx / EE;
    int h = head[idx], t = tail[idx];
    int slot = atomicAdd(&d_cursor[b * NN + t], 1);
    d_col[b * NNZ + slot] = h;
    d_val[b * NNZ + slot] = d_dinv[b * NN + h] * d_dinv[b * NN + t];
}

// smem-staged gather SpMM (R8 body verbatim): coalesced (col,val) staging into
// smem feeds the gather loop with LDS-latency addresses -> high gather MLP.
// R14's direct-__ldg variant exposed L2 latency on the index loads (689->1201us).
__global__ void k_spmm(const float* __restrict__ temp, int step) {
    const float* __restrict__ xin = (step & 1) ? d_x0 : d_x1;
    float* __restrict__ xout      = (step & 1) ? d_x1 : d_x0;
    int b = blockIdx.y, row = blockIdx.x, tid = threadIdx.x;
    int start = d_rowptr[b * (NN + 1) + row];
    int end   = d_rowptr[b * (NN + 1) + row + 1];
    float tk = temp[step];
    __shared__ int   sc[256];
    __shared__ float sv[256];
    float acc = 0.f;
    const float* xb = xin + (size_t)b * NN * DD;
    for (int base = start; base < end; base += 256) {
        int n = end - base; if (n > 256) n = 256;
        if (tid < n) {
            sc[tid] = d_col[b * NNZ + base + tid];
            sv[tid] = d_val[b * NNZ + base + tid];
        }
        __syncthreads();
        #pragma unroll 8
        for (int i = 0; i < n; i++)
            acc += sv[i] * __ldg(&xb[sc[i] * DD + tid]);
        __syncthreads();
    }
    int o = (b * NN + row) * DD + tid;
    xout[o] = acc;
    d_xcut[o] += tk * acc;
}

__global__ void k_uv(const float* __restrict__ Wp, const float* __restrict__ a_src,
                     const float* __restrict__ a_tgt) {
    int which = blockIdx.x, i = threadIdx.x;
    const float* a = which ? a_tgt : a_src;
    float acc = 0.f;
    for (int o = 0; o < DD; o++) acc += Wp[o * DD + i] * a[o];
    if (which) d_v[i] = acc; else d_u[i] = acc;
}

__global__ void k_scores() {
    int warp = threadIdx.x >> 5, lane = threadIdx.x & 31;
    int g = blockIdx.x * 8 + warp;  // node-global index over BB*NN
    const float* xr = d_xcut + (size_t)g * DD;
    float su = 0.f, svv = 0.f;
    for (int d = lane; d < DD; d += 32) {
        float xv = xr[d];
        su += xv * d_u[d];
        svv += xv * d_v[d];
    }
    for (int o = 16; o; o >>= 1) {
        su += __shfl_down_sync(0xFFFFFFFFu, su, o);
        svv += __shfl_down_sync(0xFFFFFFFFu, svv, o);
    }
    if (!lane) { d_ssrc[g] = su; d_stgt[g] = svv; }
}

__global__ void k_scatter(const int* __restrict__ head, const int* __restrict__ tail) {
    int idx = blockIdx.x * blockDim.x + threadIdx.x;
    if (idx >= BB * EE) return;
    int b = idx / EE;
    int h = head[idx], t = tail[idx];
    float z = d_ssrc[b * NN + h] + d_stgt[b * NN + t];
    // correctly-rounded double sigmoid: immune to --use_fast_math expf approximation,
    // which perturbed edge ordering near the percentile cut (R5 failure, rel_err 2.4e-2).
    float a = (float)(1.0 / (1.0 + exp(-(double)z)));
    int base = b * NN * NN;
    atomicAdd(&d_S[base + h * NN + t], a);
    atomicAdd(&d_S[base + t * NN + h], a);
    atomicAdd(&d_C[base + h * NN + t], 1);
    atomicAdd(&d_C[base + t * NN + h], 1);
}

__global__ void k_finalize() {
    int b = blockIdx.y, row = blockIdx.x, tid = threadIdx.x;
    __shared__ unsigned hist[4096];
    __shared__ int cntS;
    for (int q = tid; q < 4096; q += 256) hist[q] = 0u;
    if (tid == 0) cntS = 0;
    __syncthreads();
    int base = (b * NN + row) * NN;
    int myc = 0;
    for (int q = 0; q < 4; q++) {
        int j = q * 256 + tid;
        int c = d_C[base + j];
        float A = 0.f;
        if (c > 0) {
            A = __fdiv_rn(d_S[base + j], (float)c);
            myc++;
            atomicAdd(&hist[__float_as_uint(A) >> 20], 1u);
        }
        d_S[base + j] = A;
    }
    atomicAdd(&cntS, myc);
    __syncthreads();
    if (tid == 0) atomicAdd(&d_M[b], cntS);
    for (int q = tid; q < 4096; q += 256) {
        unsigned hv = hist[q];
        if (hv) atomicAdd(&d_h1[b * 4096 + q], hv);
    }
}

__global__ void k_select(int level) {
    int b = blockIdx.x, t = threadIdx.x;
    __shared__ unsigned part[256];
    __shared__ unsigned spre[256];
    if (level == 1 && t == 0) {
        int M = d_M[b];
        float pos = 0.2f * (float)(M - 1);
        float fl = floorf(pos);
        int lo = (int)fl;
        float frac = pos - fl;
        int hi = lo + 1; if (hi > M - 1) hi = M - 1;
        d_rankLo[b] = lo; d_rankHi[b] = hi; d_frac[b] = frac;
    }
    __syncthreads();
    int nb = (level == 3) ? 256 : 4096;
    int chunk = nb / 256;
    for (int p = 0; p < 2; p++) {
        const unsigned* hist;
        if (level == 1)      hist = d_h1 + b * 4096;
        else if (level == 2) hist = (p ? d_h2hi : d_h2lo) + b * 4096;
        else                 hist = (p ? d_h3hi : d_h3lo) + b * 256;
        int rank = p ? d_rankHi[b] : d_rankLo[b];
        unsigned c = 0;
        for (int q = 0; q < chunk; q++) c += hist[t * chunk + q];
        part[t] = c;
        spre[t] = c;
        __syncthreads();
        for (int off = 1; off < 256; off <<= 1) {
            unsigned w = (t >= off) ? spre[t - off] : 0u;
            __syncthreads();
            spre[t] += w;
            __syncthreads();
        }
        unsigned pre = spre[t] - part[t];  // exclusive prefix
        if ((unsigned)rank >= pre && (unsigned)rank < pre + part[t]) {
            unsigned r2 = (unsigned)rank - pre;
            int bin = 0;
            for (int q = 0; q < chunk; q++) {
                unsigned hv = hist[t * chunk + q];
                if (r2 < hv) { bin = t * chunk + q; break; }
                r2 -= hv;
            }
            unsigned prev = p ? d_prefHi[b] : d_prefLo[b];
            unsigned npref = (level == 1) ? (unsigned)bin
                             : ((prev << ((level == 2) ? 12 : 8)) | (unsigned)bin);
            if (p) { d_prefHi[b] = npref; d_rankHi[b] = (int)r2; }
            else   { d_prefLo[b] = npref; d_rankLo[b] = (int)r2; }
        }
        __syncthreads();
    }
    if (level == 3 && t == 0) {
        float svlo = __uint_as_float(d_prefLo[b]);
        float svhi = __uint_as_float(d_prefHi[b]);
        d_cutv[b] = svlo + d_frac[b] * (svhi - svlo);
    }
}

__global__ void k_hist2() {
    int b = blockIdx.y, row = blockIdx.x, tid = threadIdx.x;
    int base = (b * NN + row) * NN;
    unsigned pl = d_prefLo[b], ph = d_prefHi[b];
    for (int q = 0; q < 4; q++) {
        float A = d_S[base + q * 256 + tid];
        if (A > 0.f) {
            unsigned bits = __float_as_uint(A);
            unsigned top = bits >> 20, mid = (bits >> 8) & 0xFFFu;
            if (top == pl) atomicAdd(&d_h2lo[b * 4096 + mid], 1u);
            if (top == ph) atomicAdd(&d_h2hi[b * 4096 + mid], 1u);
        }
    }
}

__global__ void k_hist3() {
    int b = blockIdx.y, row = blockIdx.x, tid = threadIdx.x;
    int base = (b * NN + row) * NN;
    unsigned pl = d_prefLo[b], ph = d_prefHi[b];
    for (int q = 0; q < 4; q++) {
        float A = d_S[base + q * 256 + tid];
        if (A > 0.f) {
            unsigned bits = __float_as_uint(A);
            unsigned top24 = bits >> 8, low = bits & 0xFFu;
            if (top24 == pl) atomicAdd(&d_h3lo[b * 256 + low], 1u);
            if (top24 == ph) atomicAdd(&d_h3hi[b * 256 + low], 1u);
        }
    }
}

// Compacted row-gather: acc = sum over kept entries of row of mat (NN wide), gathering x rows.
__device__ __forceinline__ float rowgather(const float* __restrict__ matrow, float cutv,
                                           const float* __restrict__ xb, int tid,
                                           int* sidx, float* sval) {
    const float4* ar = (const float4*)matrow;
    float4 v = ar[tid];
    int c = (v.x >= cutv) + (v.y >= cutv) + (v.z >= cutv) + (v.w >= cutv);
    __shared__ int stmp[256];
    stmp[tid] = c;
    __syncthreads();
    for (int off = 1; off < 256; off <<= 1) {
        int w = (tid >= off) ? stmp[tid - off] : 0;
        __syncthreads();
        stmp[tid] += w;
        __syncthreads();
    }
    int wbase = stmp[tid] - c;  // exclusive
    int col = 4 * tid;
    if (v.x >= cutv) { sidx[wbase] = col;     sval[wbase] = v.x; wbase++; }
    if (v.y >= cutv) { sidx[wbase] = col + 1; sval[wbase] = v.y; wbase++; }
    if (v.z >= cutv) { sidx[wbase] = col + 2; sval[wbase] = v.z; wbase++; }
    if (v.w >= cutv) { sidx[wbase] = col + 3; sval[wbase] = v.w; }
    __syncthreads();
    int nnz = stmp[255];
    float acc = 0.f;
    #pragma unroll 8
    for (int i = 0; i < nnz; i++)
        acc += sval[i] * __ldg(&xb[sidx[i] * DD + tid]);
    return acc;
}

// A is symmetric => A_cut^T @ x rows == A_cut @ x rows. Compute each row once:
// store it (pooled candidates, into d_x1) and reduce |.| for the node score.
__global__ void k_outpool(const float* __restrict__ x) {
    int b = blockIdx.y, row = blockIdx.x, tid = threadIdx.x;
    __shared__ int   sidx[NN];
    __shared__ float sval[NN];
    __shared__ float red[256];
    float acc = rowgather(d_S + ((size_t)b * NN + row) * NN, d_cutv[b],
                          x + (size_t)b * NN * DD, tid, sidx, sval);
    d_x1[((size_t)b * NN + row) * DD + tid] = acc;
    red[tid] = fabsf(acc);
    __syncthreads();
    for (int off = 128; off; off >>= 1) {
        if (tid < off) red[tid] += red[tid + off];
        __syncthreads();
    }
    if (tid == 0) d_score[b * NN + row] = red[0] + 1e-7f;
}

__global__ void k_topk() {
    int b = blockIdx.x, t = threadIdx.x;
    __shared__ unsigned long long key[NN];
    float s = d_score[b * NN + t];
    unsigned bits = __float_as_uint(s);
    bits ^= (bits & 0x80000000u) ? 0xFFFFFFFFu : 0x80000000u;  // ascending orderable
    unsigned desc = ~bits;                                      // descending score
    key[t] = ((unsigned long long)desc << 32) | (unsigned)t;
    __syncthreads();
    for (int k = 2; k <= NN; k <<= 1) {
        for (int j = k >> 1; j > 0; j >>= 1) {
            int ixj = t ^ j;
            if (ixj > t) {
                bool up = ((t & k) == 0);
                unsigned long long a = key[t], bb2 = key[ixj];
                if ((a > bb2) == up) { key[t] = bb2; key[ixj] = a; }
            }
            __syncthreads();
        }
    }
    if (t < KN) d_perm[b * KN + t] = (int)(key[t] & 0xFFFFFFFFu);
}

__global__ void k_wt(const float* __restrict__ Wlin) {
    int j = blockIdx.x, o = threadIdx.x;
    d_WT[j * 256 + o] = Wlin[o * 512 + j];
}

__global__ void k_gemm(const float* __restrict__ x, const float* __restrict__ b_lin,
                       float* __restrict__ out) {
    int tile = blockIdx.x, t = threadIdx.x;
    __shared__ float sh[16][512];
    int gr0 = tile * 16;
    for (int r = 0; r < 16; r++) {
        int gr = gr0 + r;
        if (gr < ROWS_OUT) {
            int b = gr / KN, i = gr - b * KN;
            int p = d_perm[b * KN + i];
            sh[r][t]       = x[((size_t)b * NN + p) * DD + t];
            sh[r][256 + t] = d_x1[((size_t)b * NN + p) * DD + t];  // pooled row
        } else {
            sh[r][t] = 0.f; sh[r][256 + t] = 0.f;
        }
    }
    __syncthreads();
    float acc[16];
    #pragma unroll
    for (int r = 0; r < 16; r++) acc[r] = 0.f;
    for (int j = 0; j < 512; j++) {
        float w = d_WT[j * 256 + t];
        #pragma unroll
        for (int r = 0; r < 16; r++) acc[r] += sh[r][j] * w;
    }
    float bl = b_lin[t];
    for (int r = 0; r < 16; r++) {
        int gr = gr0 + r;
        if (gr < ROWS_OUT) out[(size_t)gr * DD + t] = acc[r] + bl;
    }
}

__global__ void k_misc(const int* __restrict__ labels, const int* __restrict__ ids,
                       float* __restrict__ out, int out_size) {
    int idx = blockIdx.x * blockDim.x + threadIdx.x;
    if (idx >= ROWS_OUT) return;
    int b = idx / KN, i = idx - b * KN;
    int p = d_perm[b * KN + i];
    if (out_size >= ROWS_OUT * DD + ROWS_OUT)
        out[ROWS_OUT * DD + idx] = (float)labels[b * NN + p];
    if (out_size >= ROWS_OUT * DD + 2 * ROWS_OUT)
        out[ROWS_OUT * DD + ROWS_OUT + idx] = (float)ids[b * NN + p];
}

// ---------------- launch ----------------
extern "C" void kernel_launch(void* const* d_in, const int* in_sizes, int n_in,
                              void* d_out, int out_size) {
    const float* ch     = (const float*)d_in[0];   // concept_hidden [8,1024,256]
    const int*   head   = (const int*)d_in[2];     // [8,49152]
    const int*   tail   = (const int*)d_in[3];
    const int*   labels = (const int*)d_in[5];     // [8,1024]
    const int*   ids    = (const int*)d_in[6];
    const float* temp   = (const float*)d_in[7];   // [11]
    const float* Wp     = (const float*)d_in[8];   // [256,256]
    const float* a_src  = (const float*)d_in[9];
    const float* a_tgt  = (const float*)d_in[10];
    const float* Wlin   = (const float*)d_in[11];  // [256,512]
    const float* b_lin  = (const float*)d_in[12];
    float* out = (float*)d_out;

    k_zero<<<1184, 256>>>(ch, temp);
    k_deg<<<(BB * EE + 255) / 256, 256>>>(tail);
    k_rowptr<<<BB, NN>>>();
    k_fill_edges<<<(BB * EE + 255) / 256, 256>>>(head, tail);
    for (int s = 1; s <= 10; s++)
        k_spmm<<<dim3(NN, BB), DD>>>(temp, s);
    k_uv<<<2, DD>>>(Wp, a_src, a_tgt);
    k_scores<<<(BB * NN) / 8, 256>>>();
    k_scatter<<<(BB * EE + 255) / 256, 256>>>(head, tail);
    k_finalize<<<dim3(NN, BB), 256>>>();
    k_select<<<BB, 256>>>(1);
    k_hist2<<<dim3(NN, BB), 256>>>();
    k_select<<<BB, 256>>>(2);
    k_hist3<<<dim3(NN, BB), 256>>>();
    k_select<<<BB, 256>>>(3);
    k_outpool<<<dim3(NN, BB), 256>>>(ch);
    k_topk<<<BB, NN>>>();
    k_wt<<<512, 256>>>(Wlin);
    k_gemm<<<(ROWS_OUT + 15) / 16, 256>>>(ch, b_lin, out);
    k_misc<<<(ROWS_OUT + 255) / 256, 256>>>(labels, ids, out, out_size);
}